// round 14
// baseline (speedup 1.0000x reference)
#include <cuda_runtime.h>
#include <cuda_bf16.h>
#include <limits.h>

// SHSidechainDecoder: NX=41 cube, voxel 0.3, r_max 6.0, min_sep 3, K=4.
#define GRIDG   68921            // 41^3
#define NXC     41
#define NCOL    1681             // 41*41 (i,j) columns; k contiguous in column
#define KPEAKS  4
#define NEGV    (-1.0e9f)
#define VALID_T (-1.0e8f)
#define VCAP    37056            // >= sphere voxel count (~33.5k), padded
#define THREADS 1024
#define NSEG    1024             // one segment per thread
#define NWARPS  (THREADS / 32)   // 32

// Static per-replay tables.
__device__ int g_kc[NCOL];       // k0 | (cnt<<8) per (i,j) column
__device__ int g_off[NCOL + 1];  // exclusive prefix of cnt; g_off[NCOL] = total

// Fused table build + prefix scan, single block of 1024 threads.
// Product grid: x_i = grid_xyz[3*(i*1681)], y_j = grid_xyz[3*(j*41)+1],
// z_k = grid_xyz[3*k+2]. numpy fp32 predicate sqrt((x*x+y*y)+z*z) <= 6.0
// (pairwise adds, no FMA). z_{20±m} square to identical bits and the
// predicate is monotone in m, so inside-set = |k-20| <= m_max (binary search).
__global__ __launch_bounds__(1024) void tables_kernel(
    const float* __restrict__ grid_xyz)
{
    __shared__ float s_zz[21];
    __shared__ int buf[2][NCOL];
    const int t = threadIdx.x;

    if (t < 21) {
        float z = grid_xyz[3 * (20 + t) + 2];
        s_zz[t] = __fmul_rn(z, z);
    }
    __syncthreads();

    for (int c = t; c < NCOL; c += 1024) {
        int i = c / NXC;
        int j = c - i * NXC;
        float x = grid_xyz[3 * (i * NCOL) + 0];
        float y = grid_xyz[3 * (j * NXC) + 1];
        float sxy = __fadd_rn(__fmul_rn(x, x), __fmul_rn(y, y));

        int k0 = 0, cnt = 0;
        if (__fsqrt_rn(__fadd_rn(sxy, s_zz[0])) <= 6.0f) {
            int lo = 0, hi = 20;
            while (lo < hi) {                      // largest m with pred(m)
                int mid = (lo + hi + 1) >> 1;
                if (__fsqrt_rn(__fadd_rn(sxy, s_zz[mid])) <= 6.0f) lo = mid;
                else hi = mid - 1;
            }
            k0  = 20 - lo;
            cnt = 2 * lo + 1;
        }
        g_kc[c]   = k0 | (cnt << 8);
        buf[0][c] = cnt;
    }
    __syncthreads();

    int src = 0;
    for (int off = 1; off < NCOL; off <<= 1) {
        for (int i = t; i < NCOL; i += 1024) {
            int v = buf[src][i];
            if (i >= off) v += buf[src][i - off];
            buf[1 - src][i] = v;
        }
        __syncthreads();
        src ^= 1;
    }
    for (int i = t; i < NCOL; i += 1024)
        g_off[i] = (i > 0) ? buf[src][i - 1] : 0;
    if (t == 0) g_off[NCOL] = buf[src][NCOL - 1];
}

// One block per (bn,c) slice. Masked per-column DRAM loads (~30% fewer
// sectors) scatter raw values into a compact SMEM array while each thread
// tracks a running (best, pos) IN REGISTERS — no cross-lane ops in the hot
// loop (the R8 shuffle-per-column version was issue-bound: alu 52%,
// issue 81%, dram only 13%). Hot-loop addressing is incremental (constant
// pointer steps) to minimize ALU issue. Peaks 2-4 use a 1024-segment max
// tree with dirty-segment repair after the <=343-cell NEG rewrite. Compact
// position is monotonic in g => jnp.argmax lowest-index tie-break is exact.
__global__ __launch_bounds__(THREADS) void peaks_kernel(
    const float* __restrict__ density,
    const float* __restrict__ grid_xyz,
    const float* __restrict__ Rmats,
    const float* __restrict__ tpos,
    const float* __restrict__ node_mask,
    float* __restrict__ out,
    int NC, int C)
{
    extern __shared__ char smem[];
    float* s_vals = (float*)smem;                                // [VCAP]
    int2*  s_tab  = (int2*)(smem + (size_t)VCAP * 4);            // [NCOL] {off, kc}

    __shared__ float s_segmax[NSEG];
    __shared__ int   s_segpos[NSEG];
    __shared__ int   s_dirty[NSEG];
    __shared__ float s_wval[NWARPS];
    __shared__ int   s_widx[NWARPS];
    __shared__ int   s_total;
    __shared__ float s_pk_score[KPEAKS];
    __shared__ int   s_pk_g[KPEAKS];
    __shared__ int   s_pk_i[KPEAKS], s_pk_j[KPEAKS], s_pk_k[KPEAKS];
    __shared__ int   s_pk_valid[KPEAKS];

    const int tid  = threadIdx.x;
    const int lane = tid & 31;
    const int wid  = tid >> 5;
    const int nc   = blockIdx.x;
    const float* __restrict__ slice = density + (size_t)nc * GRIDG;

    for (int i = tid; i < NCOL; i += THREADS)
        s_tab[i] = make_int2(g_off[i], g_kc[i]);
    if (tid == 0) s_total = g_off[NCOL];
    __syncthreads();
    const int total = s_total;
    const int L     = (total + NSEG - 1) / NSEG;   // segment length (~33)

    // ---- Pass 1: masked coalesced loads, compact scatter, register argmax.
    //      Fully predicated; incremental base pointer (col*NXC hoisted). ----
    float rbest = -3.0e9f;
    int   rbpos = INT_MAX;
    {
        const float* pcol = slice + wid * NXC + lane;   // &slice[col*NXC + lane]
        const int2*  ptab = s_tab + wid;
#pragma unroll 4
        for (int col = wid; col < NCOL; col += NWARPS) {
            int2 tab = *ptab;
            int  off = tab.x;
            int  k0  = tab.y & 0xff;
            int  cnt = tab.y >> 8;                 // 0..41
            bool q0 = lane < cnt;
            bool q1 = lane + 32 < cnt;
            float a = q0 ? __ldg(pcol + k0)      : 0.0f;
            float b = q1 ? __ldg(pcol + k0 + 32) : 0.0f;
            if (q0) {
                int pos = off + lane;
                s_vals[pos] = a;
                if (a > rbest) { rbest = a; rbpos = pos; } // strict >: lowest pos
            }
            if (q1) {
                int pos = off + lane + 32;
                s_vals[pos] = b;
                if (b > rbest) { rbest = b; rbpos = pos; }
            }
            pcol += NWARPS * NXC;
            ptab += NWARPS;
        }
    }
    __syncthreads();                               // scatter visible

    // ---- Segment max tree: thread t owns [t*L, min((t+1)*L, total)) ----
    {
        int b0 = tid * L;
        int b1 = b0 + L; if (b1 > total) b1 = total;
        float bv = -3.0e9f; int bp = INT_MAX;
        for (int p = b0; p < b1; ++p) {
            float v = s_vals[p];
            if (v > bv) { bv = v; bp = p; }
        }
        s_segmax[tid] = bv; s_segpos[tid] = bp;
        s_dirty[tid]  = 0;
    }

    for (int kp = 0; kp < KPEAKS; ++kp) {
        float best; int bpos;
        if (kp == 0) { best = rbest; bpos = rbpos; }
        else         { best = s_segmax[tid]; bpos = s_segpos[tid]; }

        // Block argmax reduction, min-pos tie-break.
#pragma unroll
        for (int off = 16; off > 0; off >>= 1) {
            float v2 = __shfl_down_sync(0xffffffffu, best, off);
            int   i2 = __shfl_down_sync(0xffffffffu, bpos, off);
            if (v2 > best || (v2 == best && i2 < bpos)) { best = v2; bpos = i2; }
        }
        if (lane == 0) { s_wval[wid] = best; s_widx[wid] = bpos; }
        __syncthreads();
        if (tid < 32) {
            float v  = s_wval[tid];
            int   ix = s_widx[tid];
#pragma unroll
            for (int off = 16; off > 0; off >>= 1) {
                float v2 = __shfl_down_sync(0xffffffffu, v, off);
                int   i2 = __shfl_down_sync(0xffffffffu, ix, off);
                if (v2 > v || (v2 == v && i2 < ix)) { v = v2; ix = i2; }
            }
            if (tid == 0) {
                int valid = (v > VALID_T) ? 1 : 0;
                s_pk_score[kp] = v;
                s_pk_valid[kp] = valid;
                int pos = valid ? ix : 0;
                // binary search: largest col with s_tab[col].x <= pos
                int lo = 0, hi = NCOL - 1;
                while (lo < hi) {
                    int mid = (lo + hi + 1) >> 1;
                    if (s_tab[mid].x <= pos) lo = mid; else hi = mid - 1;
                }
                int col = lo;
                int2 tab = s_tab[col];
                int kk  = (tab.y & 0xff) + (pos - tab.x);
                int ii  = col / NXC;
                s_pk_i[kp] = ii;
                s_pk_j[kp] = col - ii * NXC;
                s_pk_k[kp] = kk;
                s_pk_g[kp] = col * NXC + kk;
            }
        }
        __syncthreads();

        // ---- Chebyshev-box suppression (<=343 cells) + dirty-seg repair ----
        if (kp < KPEAKS - 1 && s_pk_valid[kp]) {
            if (tid < 343) {
                int di = tid / 49, rem = tid - di * 49;
                int dj = rem / 7,  dk  = rem - dj * 7;
                int i = s_pk_i[kp] + di - 3;
                int j = s_pk_j[kp] + dj - 3;
                int k = s_pk_k[kp] + dk - 3;
                if ((unsigned)i < NXC && (unsigned)j < NXC && (unsigned)k < NXC) {
                    int col = i * NXC + j;
                    int2 tab = s_tab[col];
                    unsigned rel = (unsigned)(k - (tab.y & 0xff));
                    if (rel < (unsigned)(tab.y >> 8)) {
                        int pos = tab.x + (int)rel;
                        s_vals[pos]      = NEGV;
                        s_dirty[pos / L] = 1;       // benign race, same value
                    }
                }
            }
            __syncthreads();
            if (s_dirty[tid]) {                     // rescan dirty segment
                int b0 = tid * L;
                int b1 = b0 + L; if (b1 > total) b1 = total;
                float bv = -3.0e9f; int bp = INT_MAX;
                for (int p = b0; p < b1; ++p) {
                    float v = s_vals[p];
                    if (v > bv) { bv = v; bp = p; }
                }
                s_segmax[tid] = bv; s_segpos[tid] = bp;
                s_dirty[tid]  = 0;
            }
            __syncthreads();
        }
    }

    // ---- Epilogue: threads 0..3 each write one peak ----
    if (tid < KPEAKS) {
        const int kk = tid;
        const int n  = nc / C;
        const float nm = node_mask[n];
        const int valid = s_pk_valid[kk];

        float x = 0.f, y = 0.f, z = 0.f;
        if (valid) {
            int ix = s_pk_g[kk];
            x = grid_xyz[3 * ix + 0];
            y = grid_xyz[3 * ix + 1];
            z = grid_xyz[3 * ix + 2];
        }
        const float* R = Rmats + (size_t)n * 9;
        const float* t = tpos  + (size_t)n * 3;
        float gx = R[0] * x + R[1] * y + R[2] * z + t[0];
        float gy = R[3] * x + R[4] * y + R[5] * z + t[1];
        float gz = R[6] * x + R[7] * y + R[8] * z + t[2];

        float score = valid ? s_pk_score[kk] : NEGV;

        const int NCK   = NC * KPEAKS;
        const int base3 = (nc * KPEAKS + kk) * 3;
        out[base3 + 0] = x * nm;                       // coords_local
        out[base3 + 1] = y * nm;
        out[base3 + 2] = z * nm;
        out[NCK * 3 + base3 + 0] = gx * nm;            // coords_global
        out[NCK * 3 + base3 + 1] = gy * nm;
        out[NCK * 3 + base3 + 2] = gz * nm;
        out[NCK * 6 + nc * KPEAKS + kk] = score * nm;  // scores
        out[NCK * 7 + nc * KPEAKS + kk] = (valid && nm != 0.0f) ? 1.0f : 0.0f; // mask
    }
}

extern "C" void kernel_launch(void* const* d_in, const int* in_sizes, int n_in,
                              void* d_out, int out_size) {
    // Inputs: density, grid_xyz, sphere_mask, coords_int, Rmats, tpos, node_mask
    const float* density   = (const float*)d_in[0];
    const float* grid_xyz  = (const float*)d_in[1];
    const float* Rmats     = (const float*)d_in[4];
    const float* tpos      = (const float*)d_in[5];
    const float* node_mask = (const float*)d_in[6];
    float* out = (float*)d_out;

    int BN = in_sizes[6];                // B*N
    int NC = in_sizes[0] / GRIDG;        // B*N*C slices
    int C  = NC / BN;

    const size_t smem_bytes = (size_t)VCAP * 4 + (size_t)NCOL * 8;
    cudaFuncSetAttribute(peaks_kernel,
                         cudaFuncAttributeMaxDynamicSharedMemorySize,
                         (int)smem_bytes);

    tables_kernel<<<1, 1024>>>(grid_xyz);
    peaks_kernel<<<NC, THREADS, smem_bytes>>>(density, grid_xyz, Rmats, tpos,
                                              node_mask, out, NC, C);
}